// round 16
// baseline (speedup 1.0000x reference)
#include <cuda_runtime.h>
#include <cuda_bf16.h>
#include <cuda_fp16.h>
#include <cstdint>

#define BB 2
#define TT 1024
#define EE 1024
#define HH 16
#define HD 64
#define NTOK (BB*TT)      // 2048
#define NBH  (BB*HH)      // 32
#define ALPHA 0.25f       // (1/sqrt(HD)) / TEMP
#define ESC 0.03125f      // exp storage scale (1/32)

typedef __nv_bfloat16  bf16;
typedef __nv_bfloat162 bf162;

// ---------------- device scratch (no allocation allowed) ----------------
__device__ bf16  g_Xhi[3][(size_t)NTOK * EE], g_Xlo[3][(size_t)NTOK * EE]; // q1,q2,key splits (bf16)
__device__ __half g_Vxf[(size_t)NTOK * EE];                                // value input, fp16 single
__device__ bf16  g_Whi[4][(size_t)EE * EE],   g_Wlo[4][(size_t)EE * EE];   // Wq,Wq2,Wq3,Wk splits (bf16)
__device__ __half g_Wf[4][(size_t)EE * EE];                                // Wv hi, Wv lo, Wo hi, Wo lo (fp16)
__device__ bf16  g_Qhi[4][(size_t)NTOK * EE], g_Qlo[4][(size_t)NTOK * EE]; // Q1,Q2,Q3,K projections (split)
__device__ __half g_Vf[(size_t)NTOK * EE];                                 // V projection, fp16 single
__device__ __half g_E1h[(size_t)NBH * TT * TT];                            // exp scores tensor1, fp16 x ESC
__device__ float g_U[3][(size_t)NBH * TT * HD];                            // unnormalized E_i @ V
__device__ __half g_AOf[(size_t)NTOK * EE];                                // attn out, fp16 single
__device__ double g_sums[3 * NBH];                                         // softmax denominators (x ESC)
__device__ unsigned int g_bar;                                             // grid handshake counter

// ---------------- low-level helpers -------------------------------------
__device__ __forceinline__ uint32_t s2u(const void* p) {
    return (uint32_t)__cvta_generic_to_shared(p);
}
__device__ __forceinline__ void cpasync16(uint32_t s, const void* g) {
    asm volatile("cp.async.cg.shared.global [%0], [%1], 16;\n" :: "r"(s), "l"(g));
}
#define CP_COMMIT asm volatile("cp.async.commit_group;\n")
#define CP_WAIT1  asm volatile("cp.async.wait_group 1;\n")
#define CP_WAIT0  asm volatile("cp.async.wait_group 0;\n")

__device__ __forceinline__ void ldsm4(uint32_t a, uint32_t& r0, uint32_t& r1, uint32_t& r2, uint32_t& r3) {
    asm volatile("ldmatrix.sync.aligned.m8n8.x4.shared.b16 {%0,%1,%2,%3}, [%4];\n"
                 : "=r"(r0), "=r"(r1), "=r"(r2), "=r"(r3) : "r"(a));
}
__device__ __forceinline__ void ldsm4t(uint32_t a, uint32_t& r0, uint32_t& r1, uint32_t& r2, uint32_t& r3) {
    asm volatile("ldmatrix.sync.aligned.m8n8.x4.trans.shared.b16 {%0,%1,%2,%3}, [%4];\n"
                 : "=r"(r0), "=r"(r1), "=r"(r2), "=r"(r3) : "r"(a));
}
__device__ __forceinline__ void mma16816(float4& d, const uint32_t* a, const uint32_t* b) {
    asm volatile(
        "mma.sync.aligned.m16n8k16.row.col.f32.bf16.bf16.f32 "
        "{%0,%1,%2,%3}, {%4,%5,%6,%7}, {%8,%9}, {%0,%1,%2,%3};\n"
        : "+f"(d.x), "+f"(d.y), "+f"(d.z), "+f"(d.w)
        : "r"(a[0]), "r"(a[1]), "r"(a[2]), "r"(a[3]),
          "r"(b[0]), "r"(b[1]));
}
__device__ __forceinline__ void mma16816f(float4& d, const uint32_t* a, const uint32_t* b) {
    asm volatile(
        "mma.sync.aligned.m16n8k16.row.col.f32.f16.f16.f32 "
        "{%0,%1,%2,%3}, {%4,%5,%6,%7}, {%8,%9}, {%0,%1,%2,%3};\n"
        : "+f"(d.x), "+f"(d.y), "+f"(d.z), "+f"(d.w)
        : "r"(a[0]), "r"(a[1]), "r"(a[2]), "r"(a[3]),
          "r"(b[0]), "r"(b[1]));
}
__device__ __forceinline__ void split1(float v, bf16& h, bf16& l) {
    h = __float2bfloat16_rn(v);
    l = __float2bfloat16_rn(v - __bfloat162float(h));
}
__device__ __forceinline__ void split1h(float v, __half& h, __half& l) {
    h = __float2half_rn(v);
    l = __float2half_rn(v - __half2float(h));
}

// ---------------- shared mma block: one k16 step (bf16 x3) ---------------
template<int SKH>
__device__ __forceinline__ void mma_block16(
    const bf16* sAh, const bf16* sAl, const bf16* sBh, const bf16* sBl,
    int ko, int wm, int wn, int lane, float4 acc[4][4])
{
    uint32_t ah[4][4], al[4][4], bh[4][2], bl[4][2];
    const int arow = wm * 64 + (lane & 15);
    const int ak = ko + (lane >> 4) * 8;
#pragma unroll
    for (int mt = 0; mt < 4; mt++) {
        ldsm4(s2u(sAh + (arow + mt * 16) * SKH + ak), ah[mt][0], ah[mt][1], ah[mt][2], ah[mt][3]);
        ldsm4(s2u(sAl + (arow + mt * 16) * SKH + ak), al[mt][0], al[mt][1], al[mt][2], al[mt][3]);
    }
    const int brow = wn * 32 + ((lane >> 4) & 1) * 8 + (lane & 7);
    const int bk = ko + ((lane >> 3) & 1) * 8;
#pragma unroll
    for (int p2 = 0; p2 < 2; p2++) {
        uint32_t r0, r1, r2, r3;
        ldsm4(s2u(sBh + (brow + p2 * 16) * SKH + bk), r0, r1, r2, r3);
        bh[p2 * 2][0] = r0; bh[p2 * 2][1] = r1; bh[p2 * 2 + 1][0] = r2; bh[p2 * 2 + 1][1] = r3;
        ldsm4(s2u(sBl + (brow + p2 * 16) * SKH + bk), r0, r1, r2, r3);
        bl[p2 * 2][0] = r0; bl[p2 * 2][1] = r1; bl[p2 * 2 + 1][0] = r2; bl[p2 * 2 + 1][1] = r3;
    }
#pragma unroll
    for (int mt = 0; mt < 4; mt++)
#pragma unroll
        for (int nt = 0; nt < 4; nt++)
            mma16816(acc[mt][nt], ah[mt], bh[nt]);
#pragma unroll
    for (int mt = 0; mt < 4; mt++)
#pragma unroll
        for (int nt = 0; nt < 4; nt++)
            mma16816(acc[mt][nt], ah[mt], bl[nt]);
#pragma unroll
    for (int mt = 0; mt < 4; mt++)
#pragma unroll
        for (int nt = 0; nt < 4; nt++)
            mma16816(acc[mt][nt], al[mt], bh[nt]);
}

// ---------------- shared mma block: one k16 step (fp16 x2) ---------------
template<int SKH>
__device__ __forceinline__ void mma_block16_f16(
    const __half* sA, const __half* sBh, const __half* sBl,
    int ko, int wm, int wn, int lane, float4 acc[4][4])
{
    uint32_t a[4][4], bh[4][2], bl[4][2];
    const int arow = wm * 64 + (lane & 15);
    const int ak = ko + (lane >> 4) * 8;
#pragma unroll
    for (int mt = 0; mt < 4; mt++)
        ldsm4(s2u(sA + (arow + mt * 16) * SKH + ak), a[mt][0], a[mt][1], a[mt][2], a[mt][3]);
    const int brow = wn * 32 + ((lane >> 4) & 1) * 8 + (lane & 7);
    const int bk = ko + ((lane >> 3) & 1) * 8;
#pragma unroll
    for (int p2 = 0; p2 < 2; p2++) {
        uint32_t r0, r1, r2, r3;
        ldsm4(s2u(sBh + (brow + p2 * 16) * SKH + bk), r0, r1, r2, r3);
        bh[p2 * 2][0] = r0; bh[p2 * 2][1] = r1; bh[p2 * 2 + 1][0] = r2; bh[p2 * 2 + 1][1] = r3;
        ldsm4(s2u(sBl + (brow + p2 * 16) * SKH + bk), r0, r1, r2, r3);
        bl[p2 * 2][0] = r0; bl[p2 * 2][1] = r1; bl[p2 * 2 + 1][0] = r2; bl[p2 * 2 + 1][1] = r3;
    }
#pragma unroll
    for (int mt = 0; mt < 4; mt++)
#pragma unroll
        for (int nt = 0; nt < 4; nt++)
            mma16816f(acc[mt][nt], a[mt], bh[nt]);
#pragma unroll
    for (int mt = 0; mt < 4; mt++)
#pragma unroll
        for (int nt = 0; nt < 4; nt++)
            mma16816f(acc[mt][nt], a[mt], bl[nt]);
}

// ---------------- unified split (ONE launch, 10 slices) -------------------
// mode 0: bf16 hi/lo ; mode 1: fp16 hi/lo ; mode 2: fp16 single (hi only)
struct SplitArgs { const float* src[10]; void* hi[10]; void* lo[10]; int mode[10]; int n4[10]; };

__global__ __launch_bounds__(256) void k_split(SplitArgs a) {
    if (blockIdx.x == 0 && blockIdx.y == 0) {
        if (threadIdx.x < 3 * NBH) g_sums[threadIdx.x] = 0.0;
        if (threadIdx.x == 96) g_bar = 0;
    }
    const int z = blockIdx.y;
    const int i = blockIdx.x * 256 + threadIdx.x;
    if (i >= a.n4[z]) return;
    float4 v = ((const float4*)a.src[z])[i];
    const int mode = a.mode[z];
    if (mode == 0) {
        bf16 h0, l0, h1, l1, h2, l2, h3, l3;
        split1(v.x, h0, l0); split1(v.y, h1, l1);
        split1(v.z, h2, l2); split1(v.w, h3, l3);
        bf162* hp = (bf162*)a.hi[z];
        bf162* lp = (bf162*)a.lo[z];
        hp[i * 2]     = __halves2bfloat162(h0, h1);
        hp[i * 2 + 1] = __halves2bfloat162(h2, h3);
        lp[i * 2]     = __halves2bfloat162(l0, l1);
        lp[i * 2 + 1] = __halves2bfloat162(l2, l3);
    } else if (mode == 1) {
        __half h0, l0, h1, l1, h2, l2, h3, l3;
        split1h(v.x, h0, l0); split1h(v.y, h1, l1);
        split1h(v.z, h2, l2); split1h(v.w, h3, l3);
        __half2* hp = (__half2*)a.hi[z];
        __half2* lp = (__half2*)a.lo[z];
        hp[i * 2]     = __halves2half2(h0, h1);
        hp[i * 2 + 1] = __halves2half2(h2, h3);
        lp[i * 2]     = __halves2half2(l0, l1);
        lp[i * 2 + 1] = __halves2half2(l2, l3);
    } else {
        __half2* hp = (__half2*)a.hi[z];
        hp[i * 2]     = __floats2half2_rn(v.x, v.y);
        hp[i * 2 + 1] = __floats2half2_rn(v.z, v.w);
    }
}

// ---------------- unified GEMM + bias, k-chunk 64, 2-stage ---------------
// mode 0: bf16 x3 (Ahi/Alo x Whi/Wlo) ; mode 1: fp16 x2 (Af x Bfh/Bfl)
struct GArg {
    const bf16 *Ahi, *Alo, *Whi, *Wlo;     // mode 0 operands
    const __half *Af, *Bfh, *Bfl;          // mode 1 operands
    const float* bias;
    bf16 *Chi, *Clo;   // bf16 split-output
    float* Cf;         // fp32 output
    __half* Ch;        // fp16 single output
    int mode;
};
struct GArgs { GArg g[5]; };

#define GEMM_SKH 72
#define GEMM_SPL (128 * GEMM_SKH)
#define GEMM_STG (4 * GEMM_SPL)
#define GEMM_SMEM (2 * GEMM_STG * 2)   // 147456 bytes

__global__ __launch_bounds__(256) void k_gemm(GArgs args) {
    extern __shared__ __align__(16) bf16 sm[];
    const GArg ga = args.g[blockIdx.z];
    const int mode = ga.mode;

    const int tid = threadIdx.x;
    const int lane = tid & 31, warp = tid >> 5;
    const int wm = warp >> 2, wn = warp & 3;
    const int m0 = blockIdx.y * 128, n0 = blockIdx.x * 128;

    const char* gb[4];
    if (mode == 0) {
        gb[0] = (const char*)ga.Ahi; gb[1] = (const char*)ga.Alo;
        gb[2] = (const char*)ga.Whi; gb[3] = (const char*)ga.Wlo;
    } else {
        gb[0] = (const char*)ga.Af;  gb[1] = nullptr;
        gb[2] = (const char*)ga.Bfh; gb[3] = (const char*)ga.Bfl;
    }

    const char* gsrc[16];
    uint32_t soff[16];
    int tile_of[16];
#pragma unroll
    for (int t = 0; t < 16; t++) {
        const int idx = tid + t * 256;
        const int tile = idx >> 10, rem = idx & 1023;
        const int row = rem >> 3, u = rem & 7;
        const int r0 = ((tile < 2) ? m0 : n0) + row;
        tile_of[t] = tile;
        gsrc[t] = gb[tile] ? gb[tile] + ((size_t)r0 * EE + u * 8) * 2 : nullptr;
        soff[t] = (uint32_t)(tile * GEMM_SPL + row * GEMM_SKH + u * 8) * 2;
    }
    const uint32_t sbase = s2u(sm);

    auto issue = [&](int kc, int p) {
#pragma unroll
        for (int t = 0; t < 16; t++)
            if (mode == 0 || tile_of[t] != 1)
                cpasync16(sbase + (uint32_t)(p * GEMM_STG) * 2 + soff[t], gsrc[t] + kc * 128);
    };
    issue(0, 0); CP_COMMIT;
    issue(1, 1); CP_COMMIT;

    float4 acc[4][4];
#pragma unroll
    for (int i = 0; i < 4; i++)
#pragma unroll
        for (int j = 0; j < 4; j++) acc[i][j] = make_float4(0.f, 0.f, 0.f, 0.f);

    for (int kc = 0; kc < EE / 64; kc++) {
        CP_WAIT1;
        __syncthreads();
        const int p = kc & 1;
        if (mode == 0) {
            const bf16* sAh = sm + p * GEMM_STG;
            const bf16* sAl = sAh + GEMM_SPL;
            const bf16* sBh = sAl + GEMM_SPL;
            const bf16* sBl = sBh + GEMM_SPL;
            mma_block16<GEMM_SKH>(sAh, sAl, sBh, sBl, 0,  wm, wn, lane, acc);
            mma_block16<GEMM_SKH>(sAh, sAl, sBh, sBl, 16, wm, wn, lane, acc);
            mma_block16<GEMM_SKH>(sAh, sAl, sBh, sBl, 32, wm, wn, lane, acc);
            mma_block16<GEMM_SKH>(sAh, sAl, sBh, sBl, 48, wm, wn, lane, acc);
        } else {
            const __half* sA  = (const __half*)(sm + p * GEMM_STG);
            const __half* sBh = sA + 2 * GEMM_SPL;
            const __half* sBl = sA + 3 * GEMM_SPL;
            mma_block16_f16<GEMM_SKH>(sA, sBh, sBl, 0,  wm, wn, lane, acc);
            mma_block16_f16<GEMM_SKH>(sA, sBh, sBl, 16, wm, wn, lane, acc);
            mma_block16_f16<GEMM_SKH>(sA, sBh, sBl, 32, wm, wn, lane, acc);
            mma_block16_f16<GEMM_SKH>(sA, sBh, sBl, 48, wm, wn, lane, acc);
        }
        __syncthreads();
        if (kc + 2 < EE / 64) issue(kc + 2, p);
        CP_COMMIT;
    }

    const int r4 = lane >> 2, q2 = (lane & 3) * 2;
#pragma unroll
    for (int mt = 0; mt < 4; mt++) {
        const int row = m0 + wm * 64 + mt * 16 + r4;
#pragma unroll
        for (int nt = 0; nt < 4; nt++) {
            const int col = n0 + wn * 32 + nt * 8 + q2;
            const float bx = ga.bias[col], by = ga.bias[col + 1];
            const float vx = acc[mt][nt].x + bx, vy = acc[mt][nt].y + by;
            const float vz = acc[mt][nt].z + bx, vw = acc[mt][nt].w + by;
            if (ga.Cf) {
                *(float2*)&ga.Cf[(size_t)row * EE + col]       = make_float2(vx, vy);
                *(float2*)&ga.Cf[(size_t)(row + 8) * EE + col] = make_float2(vz, vw);
            } else if (ga.Ch) {
                *(__half2*)&ga.Ch[(size_t)row * EE + col]       = __floats2half2_rn(vx, vy);
                *(__half2*)&ga.Ch[(size_t)(row + 8) * EE + col] = __floats2half2_rn(vz, vw);
            } else {
                bf16 h0, l0, h1, l1;
                split1(vx, h0, l0); split1(vy, h1, l1);
                *(bf162*)&ga.Chi[(size_t)row * EE + col] = __halves2bfloat162(h0, h1);
                *(bf162*)&ga.Clo[(size_t)row * EE + col] = __halves2bfloat162(l0, l1);
                split1(vz, h0, l0); split1(vw, h1, l1);
                *(bf162*)&ga.Chi[(size_t)(row + 8) * EE + col] = __halves2bfloat162(h0, h1);
                *(bf162*)&ga.Clo[(size_t)(row + 8) * EE + col] = __halves2bfloat162(l0, l1);
            }
        }
    }
}

// ---------------- fused score + AV --------------------------------------
// grid (TT/128 m-tiles, NBH, 3 tensors), block 256.
#define FS_STR 72
#define FS_QH  0
#define FS_QL  (128 * FS_STR)                  // 9216
#define FS_K   (2 * 128 * FS_STR)              // 18432; stage p at +p*18432 (hi, then lo at +9216)
#define FS_V   (FS_K + 2 * 2 * 128 * FS_STR)   // 55296; stage p at +p*9216
#define FS_W   (FS_V + 2 * 128 * FS_STR)       // 73728
#define FS_WSTR 136
#define FS_RED (FS_W + 128 * FS_WSTR)          // 91136 (halves)
#define FS_SMEM (FS_RED * 2 + 1024)            // 183296 bytes

__global__ __launch_bounds__(256) void k_score_av() {
    extern __shared__ __align__(16) __half smh[];
    float* red = (float*)(smh + FS_RED);

    const int tensor = blockIdx.z;
    const int bh = blockIdx.y;
    const int b = bh >> 4, h = bh & 15;
    const int m0 = blockIdx.x * 128;
    const size_t hofs = (size_t)b * TT * EE + h * HD;

    const bf16* Qh = g_Qhi[tensor] + hofs;
    const bf16* Ql = g_Qlo[tensor] + hofs;
    const bf16* Kh = g_Qhi[3] + hofs;
    const bf16* Kl = g_Qlo[3] + hofs;
    const __half* Vg = g_Vf + hofs;
    __half* E1 = g_E1h + (size_t)bh * TT * TT;

    const int tid = threadIdx.x;
    const int lane = tid & 31, warp = tid >> 5;
    const int wm = warp >> 2, wn = warp & 3;      // S warp tile 64x32
    const int um = warp >> 2, un = warp & 3;      // U warp tile 64x16
    const uint32_t sbase = s2u(smh);

    auto loadQ = [&]() {
#pragma unroll
        for (int t = 0; t < 8; t++) {
            const int idx = tid + t * 256;
            const int tile = idx >> 10, rem = idx & 1023;
            const int row = rem >> 3, u = rem & 7;
            const bf16* src = (tile ? Ql : Qh) + (size_t)(m0 + row) * EE + u * 8;
            cpasync16(sbase + (uint32_t)(tile * FS_QL + row * FS_STR + u * 8) * 2, src);
        }
    };
    auto loadKV = [&](int n0t, int p) {
        const int r0 = n0t * 128;
#pragma unroll
        for (int t = 0; t < 8; t++) {
            const int idx = tid + t * 256;
            const int tile = idx >> 10, rem = idx & 1023;
            const int row = rem >> 3, u = rem & 7;
            const bf16* src = (tile ? Kl : Kh) + (size_t)(r0 + row) * EE + u * 8;
            cpasync16(sbase + (uint32_t)(FS_K + p * 18432 + tile * 9216 + row * FS_STR + u * 8) * 2, src);
        }
#pragma unroll
        for (int t = 0; t < 4; t++) {
            const int idx = tid + t * 256;
            const int row = idx >> 3, u = idx & 7;
            cpasync16(sbase + (uint32_t)(FS_V + p * 9216 + row * FS_STR + u * 8) * 2,
                      Vg + (size_t)(r0 + row) * EE + u * 8);
        }
    };

    loadQ(); loadKV(0, 0); CP_COMMIT;
    loadKV(1, 1); CP_COMMIT;

    float4 uacc[4][2];
#pragma unroll
    for (int i = 0; i < 4; i++)
#pragma unroll
        for (int j = 0; j < 2; j++) uacc[i][j] = make_float4(0.f, 0.f, 0.f, 0.f);

    const int r4 = lane >> 2, q2 = (lane & 3) * 2;
    float lsum = 0.f;

    for (int n = 0; n < 8; n++) {
        const int p = n & 1;
        CP_WAIT1;
        __syncthreads();

        // ---- S-MMA ----
        float4 sacc[4][4];
#pragma unroll
        for (int i = 0; i < 4; i++)
#pragma unroll
            for (int j = 0; j < 4; j++) sacc[i][j] = make_float4(0.f, 0.f, 0.f, 0.f);
        {
            const bf16* sQh = (const bf16*)smh + FS_QH;
            const bf16* sQl = (const bf16*)smh + FS_QL;
            const bf16* sKh = (const bf16*)smh + FS_K + p * 18432;
            const bf16* sKl = sKh + 9216;
#pragma unroll
            for (int ko = 0; ko < 64; ko += 16)
                mma_block16<FS_STR>(sQh, sQl, sKh, sKl, ko, wm, wn, lane, sacc);
        }

        // ---- exp epilogue -> sW (+ E1 global for tensor 0) ----
#pragma unroll
        for (int mt = 0; mt < 4; mt++) {
            const int row = wm * 64 + mt * 16 + r4;
#pragma unroll
            for (int nt = 0; nt < 4; nt++) {
                const int col = wn * 32 + nt * 8 + q2;
                const float vx = __expf(sacc[mt][nt].x * ALPHA) * ESC;
                const float vy = __expf(sacc[mt][nt].y * ALPHA) * ESC;
                const float vz = __expf(sacc[mt][nt].z * ALPHA) * ESC;
                const float vw = __expf(sacc[mt][nt].w * ALPHA) * ESC;
                lsum += vx + vy + vz + vw;
                const __half2 hxy = __floats2half2_rn(vx, vy);
                const __half2 hzw = __floats2half2_rn(vz, vw);
                *(__half2*)&smh[FS_W + row * FS_WSTR + col]       = hxy;
                *(__half2*)&smh[FS_W + (row + 8) * FS_WSTR + col] = hzw;
                if (tensor == 0) {
                    const size_t rg = (size_t)(m0 + row) * TT + n * 128 + col;
                    *(__half2*)&E1[rg]            = hxy;
                    *(__half2*)&E1[rg + 8 * TT]   = hzw;
                }
            }
        }
        __syncthreads();

        // ---- U-MMA: U += sW(f16) @ sV(f16) ----
        {
            const __half* sW = smh + FS_W;
            const __half* sV = smh + FS_V + p * 9216;
#pragma unroll
            for (int ks = 0; ks < 128; ks += 16) {
                uint32_t aw[4][4], bv[2][2];
                const int arow = um * 64 + (lane & 15);
                const int ak = ks + (lane >> 4) * 8;
#pragma unroll
                for (int mt = 0; mt < 4; mt++)
                    ldsm4(s2u(sW + (arow + mt * 16) * FS_WSTR + ak), aw[mt][0], aw[mt][1], aw[mt][2], aw[mt][3]);
                const int srow = ks + ((lane >> 3) & 1) * 8 + (lane & 7);
                const int dcol = un * 16 + ((lane >> 4) & 1) * 8;
                {
                    uint32_t r0, r1, r2, r3;
                    ldsm4t(s2u(sV + srow * FS_STR + dcol), r0, r1, r2, r3);
                    bv[0][0] = r0; bv[0][1] = r1; bv[1][0] = r2; bv[1][1] = r3;
                }
#pragma unroll
                for (int mt = 0; mt < 4; mt++)
#pragma unroll
                    for (int nt = 0; nt < 2; nt++)
                        mma16816f(uacc[mt][nt], aw[mt], bv[nt]);
            }
        }
        __syncthreads();

        if (n + 2 < 8) loadKV(n + 2, p);
        CP_COMMIT;
    }

    // ---- writebacks ----
    float* Up = &g_U[tensor][(size_t)bh * TT * HD];
#pragma unroll
    for (int mt = 0; mt < 4; mt++) {
        const int row = m0 + um * 64 + mt * 16 + r4;
#pragma unroll
        for (int nt = 0; nt < 2; nt++) {
            const int dc = un * 16 + nt * 8 + q2;
            *(float2*)&Up[(size_t)row * HD + dc]       = make_float2(uacc[mt][nt].x, uacc[mt][nt].y);
            *(float2*)&Up[(size_t)(row + 8) * HD + dc] = make_float2(uacc[mt][nt].z, uacc[mt][nt].w);
        }
    }

    red[tid] = lsum;
    __syncthreads();
    for (int s = 128; s > 0; s >>= 1) {
        if (tid < s) red[tid] += red[tid + s];
        __syncthreads();
    }
    if (tid == 0) atomicAdd(&g_sums[tensor * 32 + bh], (double)red[0]);
}

// ---------------- fused AO-combine + output GEMM + a1 scale --------------
// Phase A (all 288 blocks): AO = (1/3) sum_i c_i U_i -> fp16, grid-stride.
// Handshake: atomic arrive; GEMM blocks wait (all blocks co-resident: 288<=296).
// Phase B: blocks [0,128) fp16-x2 GEMM out = AOf @ Wo^T + bo;
//          blocks [128,288) a1 = c1 * E1h (grid-stride, csh-cached c1).
#define OG_SKH 40
#define OG_SPL (128 * OG_SKH)          // halves per tile
#define OG_STG (3 * OG_SPL)            // A, Bh, Bl
#define OG_SMEM (2 * OG_STG * 2)       // 61440 bytes
#define OG_GEMM_BLKS 128
#define OG_A1_BLKS 160
#define OG_BLKS (OG_GEMM_BLKS + OG_A1_BLKS)

__global__ __launch_bounds__(256, 2) void k_out_a1(
    const __half* __restrict__ Af, const __half* __restrict__ Bfh,
    const __half* __restrict__ Bfl, const float* __restrict__ bias,
    float* __restrict__ Cf, float* __restrict__ a1out)
{
    extern __shared__ __align__(16) __half smo[];
    __shared__ float csh[3 * NBH];
    const int bx = blockIdx.x;
    const int tid = threadIdx.x;

    // ---- coefficients (c_i / 3 for AO; raw c1 cached for a1) ----
    if (tid < 3 * NBH) csh[tid] = (float)((double)TT / g_sums[tid]);
    __syncthreads();

    // ---- Phase A: AO combine, all blocks ----
    {
        const int N4 = NTOK * EE / 4;
        const int stride = OG_BLKS * 256;
        const float third = 1.0f / 3.0f;
        for (int g4 = bx * 256 + tid; g4 < N4; g4 += stride) {
            const int e0 = g4 * 4;
            const int tok = e0 >> 10, col = e0 & 1023;
            const int h = col >> 6, d = col & 63;
            const int bh = (tok >> 10) * 16 + h;
            const float c1 = csh[bh] * third;
            const float c2 = csh[32 + bh] * third;
            const float c3 = csh[64 + bh] * third;
            const size_t ui = ((size_t)bh * TT + (tok & 1023)) * HD + d;
            const float4 u1 = *(const float4*)&g_U[0][ui];
            const float4 u2 = *(const float4*)&g_U[1][ui];
            const float4 u3 = *(const float4*)&g_U[2][ui];
            const float v0 = u1.x * c1 + u2.x * c2 + u3.x * c3;
            const float v1 = u1.y * c1 + u2.y * c2 + u3.y * c3;
            const float v2 = u1.z * c1 + u2.z * c2 + u3.z * c3;
            const float v3 = u1.w * c1 + u2.w * c2 + u3.w * c3;
            const size_t o = (size_t)tok * EE + col;
            *(__half2*)&g_AOf[o]     = __floats2half2_rn(v0, v1);
            *(__half2*)&g_AOf[o + 2] = __floats2half2_rn(v2, v3);
        }
    }
    __threadfence();
    __syncthreads();
    if (tid == 0) atomicAdd(&g_bar, 1u);

    if (bx >= OG_GEMM_BLKS) {
        // ---- Phase B, a1 role (no dependency on AO -> no wait) ----
        const size_t N8 = (size_t)NBH * TT * TT / 8;     // uint4 elements
        const size_t stride = (size_t)OG_A1_BLKS * 256;
        for (size_t i8 = (size_t)(bx - OG_GEMM_BLKS) * 256 + tid; i8 < N8; i8 += stride) {
            const int bh = (int)(i8 >> 17);              // TT*TT/8 = 2^17 per bh
            const float c1 = csh[bh];
            const uint4 u = ((const uint4*)g_E1h)[i8];
            const float2 a = __half22float2(*(const __half2*)&u.x);
            const float2 b = __half22float2(*(const __half2*)&u.y);
            const float2 c = __half22float2(*(const __half2*)&u.z);
            const float2 d = __half22float2(*(const __half2*)&u.w);
            float4* o = (float4*)a1out + i8 * 2;
            o[0] = make_float4(a.x * c1, a.y * c1, b.x * c1, b.y * c1);
            o[1] = make_float4(c.x * c1, c.y * c1, d.x * c1, d.y * c1);
        }
        return;
    }

    // ---- Phase B, GEMM role: wait for all AO writes ----
    if (tid == 0) {
        while (atomicAdd(&g_bar, 0u) < (unsigned)OG_BLKS) ;
    }
    __syncthreads();
    __threadfence();

    const int lane = tid & 31, warp = tid >> 5;
    const int wm = warp >> 2, wn = warp & 3;
    const int m0 = (bx >> 3) * 128, n0 = (bx & 7) * 128;

    const __half* gb[3] = { Af, Bfh, Bfl };
    const __half* gsrc[6];
    uint32_t soff[6];
#pragma unroll
    for (int t = 0; t < 6; t++) {
        const int idx = tid + t * 256;
        const int tile = idx >> 9, rem = idx & 511;
        const int row = rem >> 2, u = rem & 3;
        const int r0 = (tile == 0 ? m0 : n0) + row;
        gsrc[t] = gb[tile] + (size_t)r0 * EE + u * 8;
        soff[t] = (uint32_t)(tile * OG_SPL + row * OG_SKH + u * 8) * 2;
    }
    const uint32_t sbase = s2u(smo);
    auto issue = [&](int kc, int p) {
#pragma unroll
        for (int t = 0; t < 6; t++)
            cpasync16(sbase + (uint32_t)(p * OG_STG) * 2 + soff[t], gsrc[t] + kc * 32);
    };
    issue(0, 0); CP_COMMIT;
    issue(1, 1); CP_COMMIT;

    float4 acc[4][4];
#pragma unroll
    for (int i = 0; i < 4; i++)
#pragma unroll
        for (int j = 0; j < 4; j++) acc[i][j] = make_float4(0.f, 0.f, 0.f, 0.f);

    for (int kc = 0; kc < EE / 32; kc++) {
        CP_WAIT1;
        __syncthreads();
        const int p = kc & 1;
        const __half* sA  = smo + p * OG_STG;
        const __half* sBh = sA + OG_SPL;
        const __half* sBl = sA + 2 * OG_SPL;
        mma_block16_f16<OG_SKH>(sA, sBh, sBl, 0,  wm, wn, lane, acc);
        mma_block16_f16<OG_SKH>(sA, sBh, sBl, 16, wm, wn, lane, acc);
        __syncthreads();
        if (kc + 2 < EE / 32) issue(kc + 2, p);
        CP_COMMIT;
    }

    const int r4 = lane >> 2, q2 = (lane & 3) * 2;
#pragma unroll
    for (int mt = 0; mt < 4; mt++) {
        const int row = m0 + wm * 64 + mt * 16 + r4;
#pragma unroll
        for (int nt = 0; nt < 4; nt++) {
            const int col = n0 + wn * 32 + nt * 8 + q2;
            const float bx2 = bias[col], by2 = bias[col + 1];
            *(float2*)&Cf[(size_t)row * EE + col] =
                make_float2(acc[mt][nt].x + bx2, acc[mt][nt].y + by2);
            *(float2*)&Cf[(size_t)(row + 8) * EE + col] =
                make_float2(acc[mt][nt].z + bx2, acc[mt][nt].w + by2);
        }
    }
}

// ---------------- launch ------------------------------------------------
extern "C" void kernel_launch(void* const* d_in, const int* in_sizes, int n_in,
                              void* d_out, int out_size)
{
    const float* q1  = (const float*)d_in[0];
    const float* q2  = (const float*)d_in[1];
    const float* key = (const float*)d_in[2];
    const float* val = (const float*)d_in[3];
    const float* Wq  = (const float*)d_in[4];
    const float* bq  = (const float*)d_in[5];
    const float* Wq2 = (const float*)d_in[6];
    const float* bq2 = (const float*)d_in[7];
    const float* Wq3 = (const float*)d_in[8];
    const float* bq3 = (const float*)d_in[9];
    const float* Wk  = (const float*)d_in[10];
    const float* bk  = (const float*)d_in[11];
    const float* Wv  = (const float*)d_in[12];
    const float* bv  = (const float*)d_in[13];
    const float* Wo  = (const float*)d_in[14];
    const float* bo  = (const float*)d_in[15];

    float* out = (float*)d_out;                      // [B,T,E]
    float* a1  = out + (size_t)BB * TT * EE;         // [B,H,T,T]

    bf16 *Xhi, *Xlo, *Whi, *Wlo, *Qhi, *Qlo;
    __half *Vxf, *Wf, *Vf, *AOf;
    cudaGetSymbolAddress((void**)&Xhi, g_Xhi);
    cudaGetSymbolAddress((void**)&Xlo, g_Xlo);
    cudaGetSymbolAddress((void**)&Whi, g_Whi);
    cudaGetSymbolAddress((void**)&Wlo, g_Wlo);
    cudaGetSymbolAddress((void**)&Qhi, g_Qhi);
    cudaGetSymbolAddress((void**)&Qlo, g_Qlo);
    cudaGetSymbolAddress((void**)&Vxf, g_Vxf);
    cudaGetSymbolAddress((void**)&Wf, g_Wf);
    cudaGetSymbolAddress((void**)&Vf, g_Vf);
    cudaGetSymbolAddress((void**)&AOf, g_AOf);

    static bool inited = false;
    if (!inited) {
        inited = true;
        cudaFuncSetAttribute(k_gemm, cudaFuncAttributeMaxDynamicSharedMemorySize, GEMM_SMEM);
        cudaFuncSetAttribute(k_score_av, cudaFuncAttributeMaxDynamicSharedMemorySize, FS_SMEM);
        cudaFuncSetAttribute(k_out_a1, cudaFuncAttributeMaxDynamicSharedMemorySize, OG_SMEM);
    }

    // ONE split launch: slices 0-3 = inputs, 4-9 = weights
    SplitArgs sa = {};
    const int NI4 = NTOK * EE / 4, NW4 = EE * EE / 4;
    // inputs
    const float* xs[3] = { q1, q2, key };
    for (int i = 0; i < 3; i++) {
        sa.src[i] = xs[i];
        sa.hi[i] = Xhi + (size_t)i * NTOK * EE;
        sa.lo[i] = Xlo + (size_t)i * NTOK * EE;
        sa.mode[i] = 0; sa.n4[i] = NI4;
    }
    sa.src[3] = val; sa.hi[3] = Vxf; sa.lo[3] = nullptr; sa.mode[3] = 2; sa.n4[3] = NI4;
    // weights
    const float* ws[4] = { Wq, Wq2, Wq3, Wk };
    for (int i = 0; i < 4; i++) {
        sa.src[4 + i] = ws[i];
        sa.hi[4 + i] = Whi + (size_t)i * EE * EE;
        sa.lo[4 + i] = Wlo + (size_t)i * EE * EE;
        sa.mode[4 + i] = 0; sa.n4[4 + i] = NW4;
    }
    sa.src[8] = Wv; sa.hi[8] = Wf + (size_t)0 * EE * EE; sa.lo[8] = Wf + (size_t)1 * EE * EE;
    sa.mode[8] = 1; sa.n4[8] = NW4;
    sa.src[9] = Wo; sa.hi[9] = Wf + (size_t)2 * EE * EE; sa.lo[9] = Wf + (size_t)3 * EE * EE;
    sa.mode[9] = 1; sa.n4[9] = NW4;
    k_split<<<dim3(NI4 / 256, 10), 256>>>(sa);

    // projections: Q1,Q2,Q3,K (bf16 x3) + V (fp16 x2) in one launch
    GArgs pa = {};
    const int aidx[4] = { 0, 1, 2, 2 };              // q1, q2, key, key
    const float* bs[4] = { bq, bq2, bq3, bk };
    for (int p = 0; p < 4; p++) {
        pa.g[p].mode = 0;
        pa.g[p].Ahi = Xhi + (size_t)aidx[p] * NTOK * EE;
        pa.g[p].Alo = Xlo + (size_t)aidx[p] * NTOK * EE;
        pa.g[p].Whi = Whi + (size_t)p * EE * EE;
        pa.g[p].Wlo = Wlo + (size_t)p * EE * EE;
        pa.g[p].bias = bs[p];
        pa.g[p].Chi = Qhi + (size_t)p * NTOK * EE;
        pa.g[p].Clo = Qlo + (size_t)p * NTOK * EE;
        pa.g[p].Cf = nullptr; pa.g[p].Ch = nullptr;
        pa.g[p].Af = nullptr; pa.g[p].Bfh = nullptr; pa.g[p].Bfl = nullptr;
    }
    pa.g[4].mode = 1;
    pa.g[4].Af  = Vxf;
    pa.g[4].Bfh = Wf + (size_t)0 * EE * EE;
    pa.g[4].Bfl = Wf + (size_t)1 * EE * EE;
    pa.g[4].bias = bv;
    pa.g[4].Chi = nullptr; pa.g[4].Clo = nullptr;
    pa.g[4].Cf = nullptr;  pa.g[4].Ch = Vf;
    pa.g[4].Ahi = nullptr; pa.g[4].Alo = nullptr; pa.g[4].Whi = nullptr; pa.g[4].Wlo = nullptr;
    k_gemm<<<dim3(EE / 128, NTOK / 128, 5), 256, GEMM_SMEM>>>(pa);

    // fused score + AV
    k_score_av<<<dim3(TT / 128, NBH, 3), 256, FS_SMEM>>>();

    // fused AO combine + output projection + a1 scale (one launch)
    k_out_a1<<<OG_BLKS, 256, OG_SMEM>>>(
        AOf, Wf + (size_t)2 * EE * EE, Wf + (size_t)3 * EE * EE, bo, out, a1);
}

// round 17
// speedup vs baseline: 1.0356x; 1.0356x over previous
#include <cuda_runtime.h>
#include <cuda_bf16.h>
#include <cuda_fp16.h>
#include <cstdint>

#define BB 2
#define TT 1024
#define EE 1024
#define HH 16
#define HD 64
#define NTOK (BB*TT)      // 2048
#define NBH  (BB*HH)      // 32
#define ALPHA 0.25f       // (1/sqrt(HD)) / TEMP
#define ESC 0.03125f      // exp storage scale (1/32)

typedef __nv_bfloat16  bf16;
typedef __nv_bfloat162 bf162;

// ---------------- device scratch (no allocation allowed) ----------------
__device__ bf16  g_Xhi[3][(size_t)NTOK * EE], g_Xlo[3][(size_t)NTOK * EE]; // q1,q2,key splits (bf16)
__device__ __half g_Vxf[(size_t)NTOK * EE];                                // value input, fp16 single
__device__ bf16  g_Whi[4][(size_t)EE * EE],   g_Wlo[4][(size_t)EE * EE];   // Wq,Wq2,Wq3,Wk splits (bf16)
__device__ __half g_Wf[4][(size_t)EE * EE];                                // Wv hi, Wv lo, Wo hi, Wo lo (fp16)
__device__ bf16  g_Qhi[4][(size_t)NTOK * EE], g_Qlo[4][(size_t)NTOK * EE]; // Q1,Q2,Q3,K projections (split)
__device__ __half g_Vf[(size_t)NTOK * EE];                                 // V projection, fp16 single
__device__ __half g_E1h[(size_t)NBH * TT * TT];                            // exp scores tensor1, fp16 x ESC
__device__ float g_U[3][(size_t)NBH * TT * HD];                            // unnormalized E_i @ V
__device__ __half g_AOf[(size_t)NTOK * EE];                                // attn out, fp16 single
__device__ double g_sums[3 * NBH];                                         // softmax denominators (x ESC)

// ---------------- low-level helpers -------------------------------------
__device__ __forceinline__ uint32_t s2u(const void* p) {
    return (uint32_t)__cvta_generic_to_shared(p);
}
__device__ __forceinline__ void cpasync16(uint32_t s, const void* g) {
    asm volatile("cp.async.cg.shared.global [%0], [%1], 16;\n" :: "r"(s), "l"(g));
}
#define CP_COMMIT asm volatile("cp.async.commit_group;\n")
#define CP_WAIT1  asm volatile("cp.async.wait_group 1;\n")
#define CP_WAIT0  asm volatile("cp.async.wait_group 0;\n")

__device__ __forceinline__ void ldsm4(uint32_t a, uint32_t& r0, uint32_t& r1, uint32_t& r2, uint32_t& r3) {
    asm volatile("ldmatrix.sync.aligned.m8n8.x4.shared.b16 {%0,%1,%2,%3}, [%4];\n"
                 : "=r"(r0), "=r"(r1), "=r"(r2), "=r"(r3) : "r"(a));
}
__device__ __forceinline__ void ldsm4t(uint32_t a, uint32_t& r0, uint32_t& r1, uint32_t& r2, uint32_t& r3) {
    asm volatile("ldmatrix.sync.aligned.m8n8.x4.trans.shared.b16 {%0,%1,%2,%3}, [%4];\n"
                 : "=r"(r0), "=r"(r1), "=r"(r2), "=r"(r3) : "r"(a));
}
__device__ __forceinline__ void mma16816(float4& d, const uint32_t* a, const uint32_t* b) {
    asm volatile(
        "mma.sync.aligned.m16n8k16.row.col.f32.bf16.bf16.f32 "
        "{%0,%1,%2,%3}, {%4,%5,%6,%7}, {%8,%9}, {%0,%1,%2,%3};\n"
        : "+f"(d.x), "+f"(d.y), "+f"(d.z), "+f"(d.w)
        : "r"(a[0]), "r"(a[1]), "r"(a[2]), "r"(a[3]),
          "r"(b[0]), "r"(b[1]));
}
__device__ __forceinline__ void mma16816f(float4& d, const uint32_t* a, const uint32_t* b) {
    asm volatile(
        "mma.sync.aligned.m16n8k16.row.col.f32.f16.f16.f32 "
        "{%0,%1,%2,%3}, {%4,%5,%6,%7}, {%8,%9}, {%0,%1,%2,%3};\n"
        : "+f"(d.x), "+f"(d.y), "+f"(d.z), "+f"(d.w)
        : "r"(a[0]), "r"(a[1]), "r"(a[2]), "r"(a[3]),
          "r"(b[0]), "r"(b[1]));
}
__device__ __forceinline__ void split1(float v, bf16& h, bf16& l) {
    h = __float2bfloat16_rn(v);
    l = __float2bfloat16_rn(v - __bfloat162float(h));
}
__device__ __forceinline__ void split1h(float v, __half& h, __half& l) {
    h = __float2half_rn(v);
    l = __float2half_rn(v - __half2float(h));
}

// ---------------- shared mma block: one k16 step (bf16 x3) ---------------
template<int SKH>
__device__ __forceinline__ void mma_block16(
    const bf16* sAh, const bf16* sAl, const bf16* sBh, const bf16* sBl,
    int ko, int wm, int wn, int lane, float4 acc[4][4])
{
    uint32_t ah[4][4], al[4][4], bh[4][2], bl[4][2];
    const int arow = wm * 64 + (lane & 15);
    const int ak = ko + (lane >> 4) * 8;
#pragma unroll
    for (int mt = 0; mt < 4; mt++) {
        ldsm4(s2u(sAh + (arow + mt * 16) * SKH + ak), ah[mt][0], ah[mt][1], ah[mt][2], ah[mt][3]);
        ldsm4(s2u(sAl + (arow + mt * 16) * SKH + ak), al[mt][0], al[mt][1], al[mt][2], al[mt][3]);
    }
    const int brow = wn * 32 + ((lane >> 4) & 1) * 8 + (lane & 7);
    const int bk = ko + ((lane >> 3) & 1) * 8;
#pragma unroll
    for (int p2 = 0; p2 < 2; p2++) {
        uint32_t r0, r1, r2, r3;
        ldsm4(s2u(sBh + (brow + p2 * 16) * SKH + bk), r0, r1, r2, r3);
        bh[p2 * 2][0] = r0; bh[p2 * 2][1] = r1; bh[p2 * 2 + 1][0] = r2; bh[p2 * 2 + 1][1] = r3;
        ldsm4(s2u(sBl + (brow + p2 * 16) * SKH + bk), r0, r1, r2, r3);
        bl[p2 * 2][0] = r0; bl[p2 * 2][1] = r1; bl[p2 * 2 + 1][0] = r2; bl[p2 * 2 + 1][1] = r3;
    }
#pragma unroll
    for (int mt = 0; mt < 4; mt++)
#pragma unroll
        for (int nt = 0; nt < 4; nt++)
            mma16816(acc[mt][nt], ah[mt], bh[nt]);
#pragma unroll
    for (int mt = 0; mt < 4; mt++)
#pragma unroll
        for (int nt = 0; nt < 4; nt++)
            mma16816(acc[mt][nt], ah[mt], bl[nt]);
#pragma unroll
    for (int mt = 0; mt < 4; mt++)
#pragma unroll
        for (int nt = 0; nt < 4; nt++)
            mma16816(acc[mt][nt], al[mt], bh[nt]);
}

// ---------------- shared mma block: one k16 step (fp16 x2) ---------------
template<int SKH>
__device__ __forceinline__ void mma_block16_f16(
    const __half* sA, const __half* sBh, const __half* sBl,
    int ko, int wm, int wn, int lane, float4 acc[4][4])
{
    uint32_t a[4][4], bh[4][2], bl[4][2];
    const int arow = wm * 64 + (lane & 15);
    const int ak = ko + (lane >> 4) * 8;
#pragma unroll
    for (int mt = 0; mt < 4; mt++)
        ldsm4(s2u(sA + (arow + mt * 16) * SKH + ak), a[mt][0], a[mt][1], a[mt][2], a[mt][3]);
    const int brow = wn * 32 + ((lane >> 4) & 1) * 8 + (lane & 7);
    const int bk = ko + ((lane >> 3) & 1) * 8;
#pragma unroll
    for (int p2 = 0; p2 < 2; p2++) {
        uint32_t r0, r1, r2, r3;
        ldsm4(s2u(sBh + (brow + p2 * 16) * SKH + bk), r0, r1, r2, r3);
        bh[p2 * 2][0] = r0; bh[p2 * 2][1] = r1; bh[p2 * 2 + 1][0] = r2; bh[p2 * 2 + 1][1] = r3;
        ldsm4(s2u(sBl + (brow + p2 * 16) * SKH + bk), r0, r1, r2, r3);
        bl[p2 * 2][0] = r0; bl[p2 * 2][1] = r1; bl[p2 * 2 + 1][0] = r2; bl[p2 * 2 + 1][1] = r3;
    }
#pragma unroll
    for (int mt = 0; mt < 4; mt++)
#pragma unroll
        for (int nt = 0; nt < 4; nt++)
            mma16816f(acc[mt][nt], a[mt], bh[nt]);
#pragma unroll
    for (int mt = 0; mt < 4; mt++)
#pragma unroll
        for (int nt = 0; nt < 4; nt++)
            mma16816f(acc[mt][nt], a[mt], bl[nt]);
}

// ---------------- unified split (ONE launch, 10 slices) -------------------
// mode 0: bf16 hi/lo ; mode 1: fp16 hi/lo ; mode 2: fp16 single (hi only)
struct SplitArgs { const float* src[10]; void* hi[10]; void* lo[10]; int mode[10]; int n4[10]; };

__global__ __launch_bounds__(256) void k_split(SplitArgs a) {
    if (blockIdx.x == 0 && blockIdx.y == 0 && threadIdx.x < 3 * NBH)
        g_sums[threadIdx.x] = 0.0;
    const int z = blockIdx.y;
    const int i = blockIdx.x * 256 + threadIdx.x;
    if (i >= a.n4[z]) return;
    float4 v = ((const float4*)a.src[z])[i];
    const int mode = a.mode[z];
    if (mode == 0) {
        bf16 h0, l0, h1, l1, h2, l2, h3, l3;
        split1(v.x, h0, l0); split1(v.y, h1, l1);
        split1(v.z, h2, l2); split1(v.w, h3, l3);
        bf162* hp = (bf162*)a.hi[z];
        bf162* lp = (bf162*)a.lo[z];
        hp[i * 2]     = __halves2bfloat162(h0, h1);
        hp[i * 2 + 1] = __halves2bfloat162(h2, h3);
        lp[i * 2]     = __halves2bfloat162(l0, l1);
        lp[i * 2 + 1] = __halves2bfloat162(l2, l3);
    } else if (mode == 1) {
        __half h0, l0, h1, l1, h2, l2, h3, l3;
        split1h(v.x, h0, l0); split1h(v.y, h1, l1);
        split1h(v.z, h2, l2); split1h(v.w, h3, l3);
        __half2* hp = (__half2*)a.hi[z];
        __half2* lp = (__half2*)a.lo[z];
        hp[i * 2]     = __halves2half2(h0, h1);
        hp[i * 2 + 1] = __halves2half2(h2, h3);
        lp[i * 2]     = __halves2half2(l0, l1);
        lp[i * 2 + 1] = __halves2half2(l2, l3);
    } else {
        __half2* hp = (__half2*)a.hi[z];
        hp[i * 2]     = __floats2half2_rn(v.x, v.y);
        hp[i * 2 + 1] = __floats2half2_rn(v.z, v.w);
    }
}

// ---------------- unified GEMM + bias, k-chunk 64, 2-stage ---------------
// mode 0: bf16 x3 (Ahi/Alo x Whi/Wlo) ; mode 1: fp16 x2 (Af x Bfh/Bfl)
struct GArg {
    const bf16 *Ahi, *Alo, *Whi, *Wlo;     // mode 0 operands
    const __half *Af, *Bfh, *Bfl;          // mode 1 operands
    const float* bias;
    bf16 *Chi, *Clo;   // bf16 split-output
    float* Cf;         // fp32 output
    __half* Ch;        // fp16 single output
    int mode;
};
struct GArgs { GArg g[5]; };

#define GEMM_SKH 72
#define GEMM_SPL (128 * GEMM_SKH)
#define GEMM_STG (4 * GEMM_SPL)
#define GEMM_SMEM (2 * GEMM_STG * 2)   // 147456 bytes

__global__ __launch_bounds__(256) void k_gemm(GArgs args) {
    extern __shared__ __align__(16) bf16 sm[];
    const GArg ga = args.g[blockIdx.z];
    const int mode = ga.mode;

    const int tid = threadIdx.x;
    const int lane = tid & 31, warp = tid >> 5;
    const int wm = warp >> 2, wn = warp & 3;
    const int m0 = blockIdx.y * 128, n0 = blockIdx.x * 128;

    const char* gb[4];
    if (mode == 0) {
        gb[0] = (const char*)ga.Ahi; gb[1] = (const char*)ga.Alo;
        gb[2] = (const char*)ga.Whi; gb[3] = (const char*)ga.Wlo;
    } else {
        gb[0] = (const char*)ga.Af;  gb[1] = nullptr;
        gb[2] = (const char*)ga.Bfh; gb[3] = (const char*)ga.Bfl;
    }

    const char* gsrc[16];
    uint32_t soff[16];
    int tile_of[16];
#pragma unroll
    for (int t = 0; t < 16; t++) {
        const int idx = tid + t * 256;
        const int tile = idx >> 10, rem = idx & 1023;
        const int row = rem >> 3, u = rem & 7;
        const int r0 = ((tile < 2) ? m0 : n0) + row;
        tile_of[t] = tile;
        gsrc[t] = gb[tile] ? gb[tile] + ((size_t)r0 * EE + u * 8) * 2 : nullptr;
        soff[t] = (uint32_t)(tile * GEMM_SPL + row * GEMM_SKH + u * 8) * 2;
    }
    const uint32_t sbase = s2u(sm);

    auto issue = [&](int kc, int p) {
#pragma unroll
        for (int t = 0; t < 16; t++)
            if (mode == 0 || tile_of[t] != 1)
                cpasync16(sbase + (uint32_t)(p * GEMM_STG) * 2 + soff[t], gsrc[t] + kc * 128);
    };
    issue(0, 0); CP_COMMIT;
    issue(1, 1); CP_COMMIT;

    float4 acc[4][4];
#pragma unroll
    for (int i = 0; i < 4; i++)
#pragma unroll
        for (int j = 0; j < 4; j++) acc[i][j] = make_float4(0.f, 0.f, 0.f, 0.f);

    for (int kc = 0; kc < EE / 64; kc++) {
        CP_WAIT1;
        __syncthreads();
        const int p = kc & 1;
        if (mode == 0) {
            const bf16* sAh = sm + p * GEMM_STG;
            const bf16* sAl = sAh + GEMM_SPL;
            const bf16* sBh = sAl + GEMM_SPL;
            const bf16* sBl = sBh + GEMM_SPL;
            mma_block16<GEMM_SKH>(sAh, sAl, sBh, sBl, 0,  wm, wn, lane, acc);
            mma_block16<GEMM_SKH>(sAh, sAl, sBh, sBl, 16, wm, wn, lane, acc);
            mma_block16<GEMM_SKH>(sAh, sAl, sBh, sBl, 32, wm, wn, lane, acc);
            mma_block16<GEMM_SKH>(sAh, sAl, sBh, sBl, 48, wm, wn, lane, acc);
        } else {
            const __half* sA  = (const __half*)(sm + p * GEMM_STG);
            const __half* sBh = sA + 2 * GEMM_SPL;
            const __half* sBl = sA + 3 * GEMM_SPL;
            mma_block16_f16<GEMM_SKH>(sA, sBh, sBl, 0,  wm, wn, lane, acc);
            mma_block16_f16<GEMM_SKH>(sA, sBh, sBl, 16, wm, wn, lane, acc);
            mma_block16_f16<GEMM_SKH>(sA, sBh, sBl, 32, wm, wn, lane, acc);
            mma_block16_f16<GEMM_SKH>(sA, sBh, sBl, 48, wm, wn, lane, acc);
        }
        __syncthreads();
        if (kc + 2 < EE / 64) issue(kc + 2, p);
        CP_COMMIT;
    }

    const int r4 = lane >> 2, q2 = (lane & 3) * 2;
#pragma unroll
    for (int mt = 0; mt < 4; mt++) {
        const int row = m0 + wm * 64 + mt * 16 + r4;
#pragma unroll
        for (int nt = 0; nt < 4; nt++) {
            const int col = n0 + wn * 32 + nt * 8 + q2;
            const float bx = ga.bias[col], by = ga.bias[col + 1];
            const float vx = acc[mt][nt].x + bx, vy = acc[mt][nt].y + by;
            const float vz = acc[mt][nt].z + bx, vw = acc[mt][nt].w + by;
            if (ga.Cf) {
                *(float2*)&ga.Cf[(size_t)row * EE + col]       = make_float2(vx, vy);
                *(float2*)&ga.Cf[(size_t)(row + 8) * EE + col] = make_float2(vz, vw);
            } else if (ga.Ch) {
                *(__half2*)&ga.Ch[(size_t)row * EE + col]       = __floats2half2_rn(vx, vy);
                *(__half2*)&ga.Ch[(size_t)(row + 8) * EE + col] = __floats2half2_rn(vz, vw);
            } else {
                bf16 h0, l0, h1, l1;
                split1(vx, h0, l0); split1(vy, h1, l1);
                *(bf162*)&ga.Chi[(size_t)row * EE + col] = __halves2bfloat162(h0, h1);
                *(bf162*)&ga.Clo[(size_t)row * EE + col] = __halves2bfloat162(l0, l1);
                split1(vz, h0, l0); split1(vw, h1, l1);
                *(bf162*)&ga.Chi[(size_t)(row + 8) * EE + col] = __halves2bfloat162(h0, h1);
                *(bf162*)&ga.Clo[(size_t)(row + 8) * EE + col] = __halves2bfloat162(l0, l1);
            }
        }
    }
}

// ---------------- fused score + AV --------------------------------------
// grid (TT/128 m-tiles, NBH, 3 tensors), block 256.
#define FS_STR 72
#define FS_QH  0
#define FS_QL  (128 * FS_STR)                  // 9216
#define FS_K   (2 * 128 * FS_STR)              // 18432; stage p at +p*18432 (hi, then lo at +9216)
#define FS_V   (FS_K + 2 * 2 * 128 * FS_STR)   // 55296; stage p at +p*9216
#define FS_W   (FS_V + 2 * 128 * FS_STR)       // 73728
#define FS_WSTR 136
#define FS_RED (FS_W + 128 * FS_WSTR)          // 91136 (halves)
#define FS_SMEM (FS_RED * 2 + 1024)            // 183296 bytes

__global__ __launch_bounds__(256) void k_score_av() {
    extern __shared__ __align__(16) __half smh[];
    float* red = (float*)(smh + FS_RED);

    const int tensor = blockIdx.z;
    const int bh = blockIdx.y;
    const int b = bh >> 4, h = bh & 15;
    const int m0 = blockIdx.x * 128;
    const size_t hofs = (size_t)b * TT * EE + h * HD;

    const bf16* Qh = g_Qhi[tensor] + hofs;
    const bf16* Ql = g_Qlo[tensor] + hofs;
    const bf16* Kh = g_Qhi[3] + hofs;
    const bf16* Kl = g_Qlo[3] + hofs;
    const __half* Vg = g_Vf + hofs;
    __half* E1 = g_E1h + (size_t)bh * TT * TT;

    const int tid = threadIdx.x;
    const int lane = tid & 31, warp = tid >> 5;
    const int wm = warp >> 2, wn = warp & 3;      // S warp tile 64x32
    const int um = warp >> 2, un = warp & 3;      // U warp tile 64x16
    const uint32_t sbase = s2u(smh);

    auto loadQ = [&]() {
#pragma unroll
        for (int t = 0; t < 8; t++) {
            const int idx = tid + t * 256;
            const int tile = idx >> 10, rem = idx & 1023;
            const int row = rem >> 3, u = rem & 7;
            const bf16* src = (tile ? Ql : Qh) + (size_t)(m0 + row) * EE + u * 8;
            cpasync16(sbase + (uint32_t)(tile * FS_QL + row * FS_STR + u * 8) * 2, src);
        }
    };
    auto loadKV = [&](int n0t, int p) {
        const int r0 = n0t * 128;
#pragma unroll
        for (int t = 0; t < 8; t++) {
            const int idx = tid + t * 256;
            const int tile = idx >> 10, rem = idx & 1023;
            const int row = rem >> 3, u = rem & 7;
            const bf16* src = (tile ? Kl : Kh) + (size_t)(r0 + row) * EE + u * 8;
            cpasync16(sbase + (uint32_t)(FS_K + p * 18432 + tile * 9216 + row * FS_STR + u * 8) * 2, src);
        }
#pragma unroll
        for (int t = 0; t < 4; t++) {
            const int idx = tid + t * 256;
            const int row = idx >> 3, u = idx & 7;
            cpasync16(sbase + (uint32_t)(FS_V + p * 9216 + row * FS_STR + u * 8) * 2,
                      Vg + (size_t)(r0 + row) * EE + u * 8);
        }
    };

    loadQ(); loadKV(0, 0); CP_COMMIT;
    loadKV(1, 1); CP_COMMIT;

    float4 uacc[4][2];
#pragma unroll
    for (int i = 0; i < 4; i++)
#pragma unroll
        for (int j = 0; j < 2; j++) uacc[i][j] = make_float4(0.f, 0.f, 0.f, 0.f);

    const int r4 = lane >> 2, q2 = (lane & 3) * 2;
    float lsum = 0.f;

    for (int n = 0; n < 8; n++) {
        const int p = n & 1;
        CP_WAIT1;
        __syncthreads();

        // ---- S-MMA ----
        float4 sacc[4][4];
#pragma unroll
        for (int i = 0; i < 4; i++)
#pragma unroll
            for (int j = 0; j < 4; j++) sacc[i][j] = make_float4(0.f, 0.f, 0.f, 0.f);
        {
            const bf16* sQh = (const bf16*)smh + FS_QH;
            const bf16* sQl = (const bf16*)smh + FS_QL;
            const bf16* sKh = (const bf16*)smh + FS_K + p * 18432;
            const bf16* sKl = sKh + 9216;
#pragma unroll
            for (int ko = 0; ko < 64; ko += 16)
                mma_block16<FS_STR>(sQh, sQl, sKh, sKl, ko, wm, wn, lane, sacc);
        }

        // ---- exp epilogue -> sW (+ E1 global for tensor 0) ----
#pragma unroll
        for (int mt = 0; mt < 4; mt++) {
            const int row = wm * 64 + mt * 16 + r4;
#pragma unroll
            for (int nt = 0; nt < 4; nt++) {
                const int col = wn * 32 + nt * 8 + q2;
                const float vx = __expf(sacc[mt][nt].x * ALPHA) * ESC;
                const float vy = __expf(sacc[mt][nt].y * ALPHA) * ESC;
                const float vz = __expf(sacc[mt][nt].z * ALPHA) * ESC;
                const float vw = __expf(sacc[mt][nt].w * ALPHA) * ESC;
                lsum += vx + vy + vz + vw;
                const __half2 hxy = __floats2half2_rn(vx, vy);
                const __half2 hzw = __floats2half2_rn(vz, vw);
                *(__half2*)&smh[FS_W + row * FS_WSTR + col]       = hxy;
                *(__half2*)&smh[FS_W + (row + 8) * FS_WSTR + col] = hzw;
                if (tensor == 0) {
                    const size_t rg = (size_t)(m0 + row) * TT + n * 128 + col;
                    *(__half2*)&E1[rg]            = hxy;
                    *(__half2*)&E1[rg + 8 * TT]   = hzw;
                }
            }
        }
        __syncthreads();

        // ---- U-MMA: U += sW(f16) @ sV(f16) ----
        {
            const __half* sW = smh + FS_W;
            const __half* sV = smh + FS_V + p * 9216;
#pragma unroll
            for (int ks = 0; ks < 128; ks += 16) {
                uint32_t aw[4][4], bv[2][2];
                const int arow = um * 64 + (lane & 15);
                const int ak = ks + (lane >> 4) * 8;
#pragma unroll
                for (int mt = 0; mt < 4; mt++)
                    ldsm4(s2u(sW + (arow + mt * 16) * FS_WSTR + ak), aw[mt][0], aw[mt][1], aw[mt][2], aw[mt][3]);
                const int srow = ks + ((lane >> 3) & 1) * 8 + (lane & 7);
                const int dcol = un * 16 + ((lane >> 4) & 1) * 8;
                {
                    uint32_t r0, r1, r2, r3;
                    ldsm4t(s2u(sV + srow * FS_STR + dcol), r0, r1, r2, r3);
                    bv[0][0] = r0; bv[0][1] = r1; bv[1][0] = r2; bv[1][1] = r3;
                }
#pragma unroll
                for (int mt = 0; mt < 4; mt++)
#pragma unroll
                    for (int nt = 0; nt < 2; nt++)
                        mma16816f(uacc[mt][nt], aw[mt], bv[nt]);
            }
        }
        __syncthreads();

        if (n + 2 < 8) loadKV(n + 2, p);
        CP_COMMIT;
    }

    // ---- writebacks ----
    float* Up = &g_U[tensor][(size_t)bh * TT * HD];
#pragma unroll
    for (int mt = 0; mt < 4; mt++) {
        const int row = m0 + um * 64 + mt * 16 + r4;
#pragma unroll
        for (int nt = 0; nt < 2; nt++) {
            const int dc = un * 16 + nt * 8 + q2;
            *(float2*)&Up[(size_t)row * HD + dc]       = make_float2(uacc[mt][nt].x, uacc[mt][nt].y);
            *(float2*)&Up[(size_t)(row + 8) * HD + dc] = make_float2(uacc[mt][nt].z, uacc[mt][nt].w);
        }
    }

    red[tid] = lsum;
    __syncthreads();
    for (int s = 128; s > 0; s >>= 1) {
        if (tid < s) red[tid] += red[tid + s];
        __syncthreads();
    }
    if (tid == 0) atomicAdd(&g_sums[tensor * 32 + bh], (double)red[0]);
}

// ---------------- AO = (1/3) sum_i c_i U_i -> fp16 ------------------------
__global__ __launch_bounds__(256) void k_ao() {
    const int g4 = blockIdx.x * 256 + threadIdx.x;              // float4 index
    const int e0 = g4 * 4;
    const int tok = e0 >> 10, col = e0 & 1023;
    const int h = col >> 6, d = col & 63;
    const int bh = (tok >> 10) * 16 + h;
    const float third = 1.0f / 3.0f;
    const float c1 = (float)((double)TT / g_sums[bh]) * third;
    const float c2 = (float)((double)TT / g_sums[32 + bh]) * third;
    const float c3 = (float)((double)TT / g_sums[64 + bh]) * third;
    const size_t ui = ((size_t)bh * TT + (tok & 1023)) * HD + d;
    const float4 u1 = *(const float4*)&g_U[0][ui];
    const float4 u2 = *(const float4*)&g_U[1][ui];
    const float4 u3 = *(const float4*)&g_U[2][ui];
    const float v0 = u1.x * c1 + u2.x * c2 + u3.x * c3;
    const float v1 = u1.y * c1 + u2.y * c2 + u3.y * c3;
    const float v2 = u1.z * c1 + u2.z * c2 + u3.z * c3;
    const float v3 = u1.w * c1 + u2.w * c2 + u3.w * c3;
    const size_t o = (size_t)tok * EE + col;
    *(__half2*)&g_AOf[o]     = __floats2half2_rn(v0, v1);
    *(__half2*)&g_AOf[o + 2] = __floats2half2_rn(v2, v3);
}

// ---------------- fused output GEMM + a1 scale (one wave, co-resident) ---
// blocks [0,128): fp16-x2 GEMM out = AOf @ Wo^T + bo (k-chunk 32, 2-stage,
// 60KB smem, 2 CTAs/SM). blocks [128,288): a1 = c1 * E1h, c1 cached in shared.
#define OG_SKH 40
#define OG_SPL (128 * OG_SKH)          // halves per tile
#define OG_STG (3 * OG_SPL)            // A, Bh, Bl
#define OG_SMEM (2 * OG_STG * 2)       // 61440 bytes
#define OG_GEMM_BLKS 128
#define OG_A1_BLKS 160
#define OG_BLKS (OG_GEMM_BLKS + OG_A1_BLKS)

__global__ __launch_bounds__(256, 2) void k_out_a1(
    const __half* __restrict__ Af, const __half* __restrict__ Bfh,
    const __half* __restrict__ Bfl, const float* __restrict__ bias,
    float* __restrict__ Cf, float* __restrict__ a1out)
{
    extern __shared__ __align__(16) __half smo[];
    __shared__ float csh[NBH];
    const int bx = blockIdx.x;
    const int tid = threadIdx.x;

    if (bx >= OG_GEMM_BLKS) {
        // ---- a1 role ----
        if (tid < NBH) csh[tid] = (float)((double)TT / g_sums[tid]);
        __syncthreads();
        const size_t N8 = (size_t)NBH * TT * TT / 8;     // uint4 elements
        const size_t stride = (size_t)OG_A1_BLKS * 256;
        for (size_t i8 = (size_t)(bx - OG_GEMM_BLKS) * 256 + tid; i8 < N8; i8 += stride) {
            const int bh = (int)(i8 >> 17);              // TT*TT/8 = 2^17 per bh
            const float c1 = csh[bh];
            const uint4 u = ((const uint4*)g_E1h)[i8];
            const float2 a = __half22float2(*(const __half2*)&u.x);
            const float2 b = __half22float2(*(const __half2*)&u.y);
            const float2 c = __half22float2(*(const __half2*)&u.z);
            const float2 d = __half22float2(*(const __half2*)&u.w);
            float4* o = (float4*)a1out + i8 * 2;
            o[0] = make_float4(a.x * c1, a.y * c1, b.x * c1, b.y * c1);
            o[1] = make_float4(c.x * c1, c.y * c1, d.x * c1, d.y * c1);
        }
        return;
    }

    // ---- GEMM role ----
    const int lane = tid & 31, warp = tid >> 5;
    const int wm = warp >> 2, wn = warp & 3;
    const int m0 = (bx >> 3) * 128, n0 = (bx & 7) * 128;

    const __half* gb[3] = { Af, Bfh, Bfl };
    const __half* gsrc[6];
    uint32_t soff[6];
#pragma unroll
    for (int t = 0; t < 6; t++) {
        const int idx = tid + t * 256;
        const int tile = idx >> 9, rem = idx & 511;
        const int row = rem >> 2, u = rem & 3;
        const int r0 = (tile == 0 ? m0 : n0) + row;
        gsrc[t] = gb[tile] + (size_t)r0 * EE + u * 8;
        soff[t] = (uint32_t)(tile * OG_SPL + row * OG_SKH + u * 8) * 2;
    }
    const uint32_t sbase = s2u(smo);
    auto issue = [&](int kc, int p) {
#pragma unroll
        for (int t = 0; t < 6; t++)
            cpasync16(sbase + (uint32_t)(p * OG_STG) * 2 + soff[t], gsrc[t] + kc * 32);
    };
    issue(0, 0); CP_COMMIT;
    issue(1, 1); CP_COMMIT;

    float4 acc[4][4];
#pragma unroll
    for (int i = 0; i < 4; i++)
#pragma unroll
        for (int j = 0; j < 4; j++) acc[i][j] = make_float4(0.f, 0.f, 0.f, 0.f);

    for (int kc = 0; kc < EE / 32; kc++) {
        CP_WAIT1;
        __syncthreads();
        const int p = kc & 1;
        const __half* sA  = smo + p * OG_STG;
        const __half* sBh = sA + OG_SPL;
        const __half* sBl = sA + 2 * OG_SPL;
        mma_block16_f16<OG_SKH>(sA, sBh, sBl, 0,  wm, wn, lane, acc);
        mma_block16_f16<OG_SKH>(sA, sBh, sBl, 16, wm, wn, lane, acc);
        __syncthreads();
        if (kc + 2 < EE / 32) issue(kc + 2, p);
        CP_COMMIT;
    }

    const int r4 = lane >> 2, q2 = (lane & 3) * 2;
#pragma unroll
    for (int mt = 0; mt < 4; mt++) {
        const int row = m0 + wm * 64 + mt * 16 + r4;
#pragma unroll
        for (int nt = 0; nt < 4; nt++) {
            const int col = n0 + wn * 32 + nt * 8 + q2;
            const float bx2 = bias[col], by2 = bias[col + 1];
            *(float2*)&Cf[(size_t)row * EE + col] =
                make_float2(acc[mt][nt].x + bx2, acc[mt][nt].y + by2);
            *(float2*)&Cf[(size_t)(row + 8) * EE + col] =
                make_float2(acc[mt][nt].z + bx2, acc[mt][nt].w + by2);
        }
    }
}

// ---------------- launch ------------------------------------------------
extern "C" void kernel_launch(void* const* d_in, const int* in_sizes, int n_in,
                              void* d_out, int out_size)
{
    const float* q1  = (const float*)d_in[0];
    const float* q2  = (const float*)d_in[1];
    const float* key = (const float*)d_in[2];
    const float* val = (const float*)d_in[3];
    const float* Wq  = (const float*)d_in[4];
    const float* bq  = (const float*)d_in[5];
    const float* Wq2 = (const float*)d_in[6];
    const float* bq2 = (const float*)d_in[7];
    const float* Wq3 = (const float*)d_in[8];
    const float* bq3 = (const float*)d_in[9];
    const float* Wk  = (const float*)d_in[10];
    const float* bk  = (const float*)d_in[11];
    const float* Wv  = (const float*)d_in[12];
    const float* bv  = (const float*)d_in[13];
    const float* Wo  = (const float*)d_in[14];
    const float* bo  = (const float*)d_in[15];

    float* out = (float*)d_out;                      // [B,T,E]
    float* a1  = out + (size_t)BB * TT * EE;         // [B,H,T,T]

    bf16 *Xhi, *Xlo, *Whi, *Wlo, *Qhi, *Qlo;
    __half *Vxf, *Wf, *Vf, *AOf;
    cudaGetSymbolAddress((void**)&Xhi, g_Xhi);
    cudaGetSymbolAddress((void**)&Xlo, g_Xlo);
    cudaGetSymbolAddress((void**)&Whi, g_Whi);
    cudaGetSymbolAddress((void**)&Wlo, g_Wlo);
    cudaGetSymbolAddress((void**)&Qhi, g_Qhi);
    cudaGetSymbolAddress((void**)&Qlo, g_Qlo);
    cudaGetSymbolAddress((void**)&Vxf, g_Vxf);
    cudaGetSymbolAddress((void**)&Wf, g_Wf);
    cudaGetSymbolAddress((void**)&Vf, g_Vf);
    cudaGetSymbolAddress((void**)&AOf, g_AOf);

    static bool inited = false;
    if (!inited) {
        inited = true;
        cudaFuncSetAttribute(k_gemm, cudaFuncAttributeMaxDynamicSharedMemorySize, GEMM_SMEM);
        cudaFuncSetAttribute(k_score_av, cudaFuncAttributeMaxDynamicSharedMemorySize, FS_SMEM);
        cudaFuncSetAttribute(k_out_a1, cudaFuncAttributeMaxDynamicSharedMemorySize, OG_SMEM);
    }

    // ONE split launch: slices 0-3 = inputs, 4-9 = weights
    SplitArgs sa = {};
    const int NI4 = NTOK * EE / 4, NW4 = EE * EE / 4;
    const float* xs[3] = { q1, q2, key };
    for (int i = 0; i < 3; i++) {
        sa.src[i] = xs[i];
        sa.hi[i] = Xhi + (size_t)i * NTOK * EE;
        sa.lo[i] = Xlo + (size_t)i * NTOK * EE;
        sa.mode[i] = 0; sa.n4[i] = NI4;
    }
    sa.src[3] = val; sa.hi[3] = Vxf; sa.lo[3] = nullptr; sa.mode[3] = 2; sa.n4[3] = NI4;
    const float* ws[4] = { Wq, Wq2, Wq3, Wk };
    for (int i = 0; i < 4; i++) {
        sa.src[4 + i] = ws[i];
        sa.hi[4 + i] = Whi + (size_t)i * EE * EE;
        sa.lo[4 + i] = Wlo + (size_t)i * EE * EE;
        sa.mode[4 + i] = 0; sa.n4[4 + i] = NW4;
    }
    sa.src[8] = Wv; sa.hi[8] = Wf + (size_t)0 * EE * EE; sa.lo[8] = Wf + (size_t)1 * EE * EE;
    sa.mode[8] = 1; sa.n4[8] = NW4;
    sa.src[9] = Wo; sa.hi[9] = Wf + (size_t)2 * EE * EE; sa.lo[9] = Wf + (size_t)3 * EE * EE;
    sa.mode[9] = 1; sa.n4[9] = NW4;
    k_split<<<dim3(NI4 / 256, 10), 256>>>(sa);

    // projections: Q1,Q2,Q3,K (bf16 x3) + V (fp16 x2) in one launch
    GArgs pa = {};
    const int aidx[4] = { 0, 1, 2, 2 };              // q1, q2, key, key
    const float* bs[4] = { bq, bq2, bq3, bk };
    for (int p = 0; p < 4; p++) {
        pa.g[p].mode = 0;
        pa.g[p].Ahi = Xhi + (size_t)aidx[p] * NTOK * EE;
        pa.g[p].Alo = Xlo + (size_t)aidx[p] * NTOK * EE;
        pa.g[p].Whi = Whi + (size_t)p * EE * EE;
        pa.g[p].Wlo = Wlo + (size_t)p * EE * EE;
        pa.g[p].bias = bs[p];
        pa.g[p].Chi = Qhi + (size_t)p * NTOK * EE;
        pa.g[p].Clo = Qlo + (size_t)p * NTOK * EE;
        pa.g[p].Cf = nullptr; pa.g[p].Ch = nullptr;
        pa.g[p].Af = nullptr; pa.g[p].Bfh = nullptr; pa.g[p].Bfl = nullptr;
    }
    pa.g[4].mode = 1;
    pa.g[4].Af  = Vxf;
    pa.g[4].Bfh = Wf + (size_t)0 * EE * EE;
    pa.g[4].Bfl = Wf + (size_t)1 * EE * EE;
    pa.g[4].bias = bv;
    pa.g[4].Chi = nullptr; pa.g[4].Clo = nullptr;
    pa.g[4].Cf = nullptr;  pa.g[4].Ch = Vf;
    pa.g[4].Ahi = nullptr; pa.g[4].Alo = nullptr; pa.g[4].Whi = nullptr; pa.g[4].Wlo = nullptr;
    k_gemm<<<dim3(EE / 128, NTOK / 128, 5), 256, GEMM_SMEM>>>(pa);

    // fused score + AV
    k_score_av<<<dim3(TT / 128, NBH, 3), 256, FS_SMEM>>>();

    // AO combine (fp16 out)
    k_ao<<<(NTOK * EE / 4) / 256, 256>>>();

    // fused output projection + a1 scale (single wave, co-resident roles)
    k_out_a1<<<OG_BLKS, 256, OG_SMEM>>>(
        AOf, Wf + (size_t)2 * EE * EE, Wf + (size_t)3 * EE * EE, bo, out, a1);
}